// round 1
// baseline (speedup 1.0000x reference)
#include <cuda_runtime.h>
#include <math.h>

#define Bb   16
#define Cc   128
#define Hh   64
#define Ww   64
#define HID  128
#define OC   512   // 4*HID
#define KK   3

// Scratch (device globals: allocation-free per harness rules)
__device__ float g_zis[(size_t)Bb*OC*Hh*Ww];   // [b, o, h, w]  134 MB
__device__ float g_ztmp[Bb*OC*Ww];             // [b, o, w] current row pre-activation
__device__ float g_h[Bb*HID*Ww];               // hidden state (prev row)
__device__ float g_c[Bb*HID*Ww];               // cell state

// ---------------------------------------------------------------------------
__global__ void init_state_kernel() {
    int i = blockIdx.x * blockDim.x + threadIdx.x;
    if (i < Bb*HID*Ww) { g_h[i] = 0.f; g_c[i] = 0.f; }
}

// ---------------------------------------------------------------------------
// Phase 1: masked input-to-state conv.
// z_is[b,o,h,w] = b_is[o] + sum_c ( x[b,c,h,w-1]*W_is[o,c,0,0] + x[b,c,h,w]*W_is[o,c,0,1] )
// grid: (B*H, OC/64), block 256 = 16(tx:w) x 16(ty:o), 4x4 register tile.
// dyn smem: xs[128][64] + w0[128][64] + w1[128][64] = 96 KB
__global__ void kA_zis(const float* __restrict__ x,
                       const float* __restrict__ Wis,
                       const float* __restrict__ bis) {
    extern __shared__ float sm[];
    float* xs = sm;                 // [c][w]
    float* w0 = sm + 128*64;        // [c][o_local]
    float* w1 = w0 + 128*64;

    int bh = blockIdx.x;
    int b  = bh >> 6;
    int h  = bh & 63;
    int o0 = blockIdx.y * 64;
    int tid = threadIdx.x;

    // load x row [128 c][64 w], coalesced in w
    for (int idx = tid; idx < 128*64; idx += 256) {
        int c = idx >> 6, w = idx & 63;
        xs[idx] = x[(((size_t)b*Cc + c)*Hh + h)*Ww + w];
    }
    // load weight tile: contiguous 64*384 floats starting at o0*384 (coalesced),
    // scatter taps k=0,1 into [c][o_local] layout, drop k=2 (masked).
    {
        const float* wsrc = Wis + (size_t)o0 * (Cc*KK);
        for (int idx = tid; idx < 64*Cc*KK; idx += 256) {
            float v = wsrc[idx];
            int ol  = idx / (Cc*KK);
            int rem = idx - ol*(Cc*KK);
            int c   = rem / KK;
            int k   = rem - c*KK;
            if (k == 0)      w0[c*64 + ol] = v;
            else if (k == 1) w1[c*64 + ol] = v;
        }
    }
    __syncthreads();

    int tx = tid & 15, ty = tid >> 4;
    int wb = tx * 4;                 // w base
    float acc[4][4];
#pragma unroll
    for (int j = 0; j < 4; ++j)
#pragma unroll
        for (int i = 0; i < 4; ++i) acc[j][i] = 0.f;

#pragma unroll 4
    for (int c = 0; c < 128; ++c) {
        float4 xv = *reinterpret_cast<const float4*>(&xs[c*64 + wb]);
        float  xm1 = (wb == 0) ? 0.f : xs[c*64 + wb - 1];
        float4 a0 = *reinterpret_cast<const float4*>(&w0[c*64 + ty*4]);
        float4 a1 = *reinterpret_cast<const float4*>(&w1[c*64 + ty*4]);
        float xc[4] = {xv.x, xv.y, xv.z, xv.w};
        float xp[4] = {xm1,  xv.x, xv.y, xv.z};
        float W0a[4] = {a0.x, a0.y, a0.z, a0.w};
        float W1a[4] = {a1.x, a1.y, a1.z, a1.w};
#pragma unroll
        for (int j = 0; j < 4; ++j)
#pragma unroll
            for (int i = 0; i < 4; ++i)
                acc[j][i] += W1a[j]*xc[i] + W0a[j]*xp[i];
    }

#pragma unroll
    for (int j = 0; j < 4; ++j) {
        int o = o0 + ty*4 + j;
        float bv = bis[o];
        float4 r;
        r.x = acc[j][0] + bv; r.y = acc[j][1] + bv;
        r.z = acc[j][2] + bv; r.w = acc[j][3] + bv;
        *reinterpret_cast<float4*>(&g_zis[(((size_t)b*OC + o)*Hh + h)*Ww + wb]) = r;
    }
}

// ---------------------------------------------------------------------------
// Phase 2a: state-to-state conv for one row.
// g_ztmp[b,o,w] = g_zis[b,o,row,w] + b_ss[o] + sum_c sum_k h[b,c,w+k-1]*W_ss[o,c,0,k]
// grid: (B, OC/64), block 256 (16x16), 4x4 register tile.
// dyn smem: hs[128][68] (w+1 offset, padded) + wk[3][128][64] = 133120 B
__global__ void kB_row(const float* __restrict__ Wss,
                       const float* __restrict__ bss,
                       int row) {
    extern __shared__ float sm[];
    float* hs = sm;                 // [c][68], hs[c*68 + (w+1)]
    float* wk = sm + 128*68;        // [k][c][o_local]

    int b  = blockIdx.x;
    int o0 = blockIdx.y * 64;
    int tid = threadIdx.x;

    for (int idx = tid; idx < 128*68; idx += 256) {
        int c = idx / 68, p = idx - c*68;
        int w = p - 1;
        float v = 0.f;
        if (w >= 0 && w < Ww) v = g_h[(b*HID + c)*Ww + w];
        hs[idx] = v;
    }
    {
        const float* wsrc = Wss + (size_t)o0 * (HID*KK);
        for (int idx = tid; idx < 64*HID*KK; idx += 256) {
            float v = wsrc[idx];
            int ol  = idx / (HID*KK);
            int rem = idx - ol*(HID*KK);
            int c   = rem / KK;
            int k   = rem - c*KK;
            wk[k*8192 + c*64 + ol] = v;
        }
    }
    __syncthreads();

    int tx = tid & 15, ty = tid >> 4;
    int wb = tx * 4;
    float acc[4][4];
#pragma unroll
    for (int j = 0; j < 4; ++j)
#pragma unroll
        for (int i = 0; i < 4; ++i) acc[j][i] = 0.f;

#pragma unroll 2
    for (int c = 0; c < 128; ++c) {
        const float* hrow = &hs[c*68 + wb];   // hrow[t] = h[wb - 1 + t]
        float4 hv = *reinterpret_cast<const float4*>(hrow);
        float  h4 = hrow[4];
        float  h5 = hrow[5];
        float hvals[6] = {hv.x, hv.y, hv.z, hv.w, h4, h5};
#pragma unroll
        for (int k = 0; k < 3; ++k) {
            float4 wv = *reinterpret_cast<const float4*>(&wk[k*8192 + c*64 + ty*4]);
            float Wa[4] = {wv.x, wv.y, wv.z, wv.w};
#pragma unroll
            for (int j = 0; j < 4; ++j)
#pragma unroll
                for (int i = 0; i < 4; ++i)
                    acc[j][i] += Wa[j] * hvals[i + k];
        }
    }

#pragma unroll
    for (int j = 0; j < 4; ++j) {
        int o = o0 + ty*4 + j;
        float bv = bss[o];
        const float4 zi = *reinterpret_cast<const float4*>(
            &g_zis[(((size_t)b*OC + o)*Hh + row)*Ww + wb]);
        float4 r;
        r.x = acc[j][0] + bv + zi.x;
        r.y = acc[j][1] + bv + zi.y;
        r.z = acc[j][2] + bv + zi.z;
        r.w = acc[j][3] + bv + zi.w;
        *reinterpret_cast<float4*>(&g_ztmp[((size_t)b*OC + o)*Ww + wb]) = r;
    }
}

// ---------------------------------------------------------------------------
// Phase 2b: LSTM gates elementwise, update state, write output row.
__global__ void kC_gates(float* __restrict__ out, int row) {
    int idx = blockIdx.x * blockDim.x + threadIdx.x;
    if (idx >= Bb*HID*Ww) return;
    int b  = idx / (HID*Ww);
    int r  = idx - b*(HID*Ww);
    int ch = r / Ww;
    int w  = r - ch*Ww;

    int zb = (b*OC + ch)*Ww + w;
    float zi = g_ztmp[zb];
    float zf = g_ztmp[zb + 1*HID*Ww];
    float zo = g_ztmp[zb + 2*HID*Ww];
    float zg = g_ztmp[zb + 3*HID*Ww];

    float ig = 1.f / (1.f + __expf(-zi));
    float fg = 1.f / (1.f + __expf(-zf));
    float og = 1.f / (1.f + __expf(-zo));
    float g  = tanhf(zg);

    float cn = fg * g_c[idx] + ig * g;
    float hn = og * tanhf(cn);
    g_c[idx] = cn;
    g_h[idx] = hn;
    out[(((size_t)b*HID + ch)*Hh + row)*Ww + w] = hn;
}

// ---------------------------------------------------------------------------
extern "C" void kernel_launch(void* const* d_in, const int* in_sizes, int n_in,
                              void* d_out, int out_size) {
    const float* x   = (const float*)d_in[0];
    const float* Wis = (const float*)d_in[1];
    const float* bis = (const float*)d_in[2];
    const float* Wss = (const float*)d_in[3];
    const float* bss = (const float*)d_in[4];
    float* out = (float*)d_out;

    const int SMEM_A = 3 * 128 * 64 * sizeof(float);          // 98304
    const int SMEM_B = (128*68 + 3*128*64) * sizeof(float);   // 133120
    cudaFuncSetAttribute(kA_zis, cudaFuncAttributeMaxDynamicSharedMemorySize, SMEM_A);
    cudaFuncSetAttribute(kB_row, cudaFuncAttributeMaxDynamicSharedMemorySize, SMEM_B);

    init_state_kernel<<<(Bb*HID*Ww + 255)/256, 256>>>();

    dim3 gA(Bb*Hh, OC/64);
    kA_zis<<<gA, 256, SMEM_A>>>(x, Wis, bis);

    dim3 gB(Bb, OC/64);
    for (int r = 0; r < Hh; ++r) {
        kB_row<<<gB, 256, SMEM_B>>>(Wss, bss, r);
        kC_gates<<<(Bb*HID*Ww + 255)/256, 256>>>(out, r);
    }
}

// round 2
// speedup vs baseline: 1.6738x; 1.6738x over previous
#include <cuda_runtime.h>
#include <math.h>

#define Bb   16
#define Cc   128
#define Hh   64
#define Ww   64
#define HID  128
#define OC   512   // 4*HID
#define NCTA 128   // persistent grid (16 b x 8 hid-blocks)

// Scratch (device globals: allocation-free per harness rules)
__device__ float g_zis[(size_t)Bb*OC*Hh*Ww];     // [b, o, h, w]  134 MB
__device__ float g_hbuf[2][Bb*HID*Ww];           // double-buffered hidden state
__device__ volatile unsigned g_bar;              // grid barrier counter

// ---- packed f32x2 helpers (sm_103a) --------------------------------------
#define PACK2(d, lo, hi) asm("mov.b64 %0, {%1,%2};" : "=l"(d) : "f"(lo), "f"(hi))
#define FMA2(d, a, b, c) asm("fma.rn.f32x2 %0, %1, %2, %3;" : "=l"(d) : "l"(a), "l"(b), "l"(c))
#define UNPK2(lo, hi, s) asm("mov.b64 {%0,%1}, %2;" : "=f"(lo), "=f"(hi) : "l"(s))

// ---------------------------------------------------------------------------
__global__ void init_kernel() { g_bar = 0u; }

// ---------------------------------------------------------------------------
// Phase 1: masked input-to-state conv (taps k=0,1; k=2 masked away).
// z_is[b,o,h,w] = b_is[o] + sum_c ( x[b,c,h,w-1]*W[o,c,0,0] + x[b,c,h,w]*W[o,c,0,1] )
// grid (B*H, OC/64), block 256 = 16(w)x16(o), 4w x 4o per thread, o paired f32x2.
__global__ void kA_zis(const float* __restrict__ x,
                       const float* __restrict__ Wis,
                       const float* __restrict__ bis) {
    extern __shared__ float sm[];
    float* xs = sm;               // [c][64]
    float* w0 = sm + 8192;        // [c][o_local]
    float* w1 = w0 + 8192;

    int b  = blockIdx.x >> 6;
    int h  = blockIdx.x & 63;
    int o0 = blockIdx.y * 64;
    int tid = threadIdx.x;

    for (int idx = tid; idx < 8192; idx += 256)
        xs[idx] = x[(((size_t)b*Cc + (idx >> 6))*Hh + h)*Ww + (idx & 63)];

    {   // coalesced weight read, scatter taps 0,1 into [c][o_local]
        const float* wsrc = Wis + (size_t)o0 * (Cc*3);
        for (int idx = tid; idx < 64*Cc*3; idx += 256) {
            float v = wsrc[idx];
            int ol  = idx / (Cc*3);
            int rem = idx - ol*(Cc*3);
            int c   = rem / 3;
            int k   = rem - c*3;
            if (k == 0)      w0[c*64 + ol] = v;
            else if (k == 1) w1[c*64 + ol] = v;
        }
    }
    __syncthreads();

    int tx = tid & 15, ty = tid >> 4;
    int wb = tx * 4;

    unsigned long long acc[2][4];
#pragma unroll
    for (int jp = 0; jp < 2; ++jp)
#pragma unroll
        for (int i = 0; i < 4; ++i) acc[jp][i] = 0ull;

#pragma unroll 2
    for (int c = 0; c < 128; ++c) {
        const float* xr = &xs[c*64 + wb];
        float4 xv = *reinterpret_cast<const float4*>(xr);
        float xm1 = (wb == 0) ? 0.f : xr[-1];
        float hv[5] = {xm1, xv.x, xv.y, xv.z, xv.w};
        unsigned long long hp[5];
#pragma unroll
        for (int t = 0; t < 5; ++t) PACK2(hp[t], hv[t], hv[t]);
#pragma unroll
        for (int jp = 0; jp < 2; ++jp) {
            unsigned long long w0p = *reinterpret_cast<const unsigned long long*>(&w0[c*64 + ty*4 + 2*jp]);
            unsigned long long w1p = *reinterpret_cast<const unsigned long long*>(&w1[c*64 + ty*4 + 2*jp]);
#pragma unroll
            for (int i = 0; i < 4; ++i) {
                FMA2(acc[jp][i], w0p, hp[i],   acc[jp][i]);   // tap k=0 uses x[w-1]
                FMA2(acc[jp][i], w1p, hp[i+1], acc[jp][i]);   // tap k=1 uses x[w]
            }
        }
    }

#pragma unroll
    for (int jp = 0; jp < 2; ++jp) {
        float lo[4], hi[4];
#pragma unroll
        for (int i = 0; i < 4; ++i) UNPK2(lo[i], hi[i], acc[jp][i]);
        int oA = o0 + ty*4 + 2*jp;
        float bA = bis[oA], bB = bis[oA+1];
        float4 rA = {lo[0]+bA, lo[1]+bA, lo[2]+bA, lo[3]+bA};
        float4 rB = {hi[0]+bB, hi[1]+bB, hi[2]+bB, hi[3]+bB};
        *reinterpret_cast<float4*>(&g_zis[(((size_t)b*OC + oA  )*Hh + h)*Ww + wb]) = rA;
        *reinterpret_cast<float4*>(&g_zis[(((size_t)b*OC + oA+1)*Hh + h)*Ww + wb]) = rB;
    }
}

// ---------------------------------------------------------------------------
// Phase 2: persistent fused row-recurrence. 128 CTAs, each owns (b, hb):
// o-channels { g*128 + hb*16 + l : g in 0..3, l in 0..15 }, so it can compute
// LSTM gates for hid channels hb*16..hb*16+15 locally. Weights stay in smem
// across all 64 rows; cell state lives in registers; grid barrier per row.
__global__ void __launch_bounds__(256, 1)
kP_rows(const float* __restrict__ Wss,
        const float* __restrict__ bss,
        float* __restrict__ out) {
    extern __shared__ float sm[];
    float* wk   = sm;                    // [3][128][64]  24576 floats
    float* hs   = sm + 3*8192;           // [128][68], h at offset +1
    float* zbuf = hs + 128*68;           // [64][66]  z_ss staged for gates

    int cta = blockIdx.x;
    int b   = cta >> 3;
    int hb  = cta & 7;
    int tid = threadIdx.x;
    int tx  = tid & 15, ty = tid >> 4;
    int wb  = tx * 4;

    // Load W_ss once: o_local = g*16 + l  ->  global o = g*128 + hb*16 + l
    for (int idx = tid; idx < 64*HID*3; idx += 256) {
        int ol  = idx / (HID*3);
        int rem = idx - ol*(HID*3);
        int g   = ol >> 4, l = ol & 15;
        int o   = g*128 + hb*16 + l;
        float v = Wss[(size_t)o*(HID*3) + rem];
        int c = rem / 3, k = rem - c*3;
        wk[k*8192 + c*64 + ol] = v;
    }
    // zero hs (covers w=-1 / w=64 borders for all rows; row 0 uses all-zero h)
    for (int idx = tid; idx < 128*68; idx += 256) hs[idx] = 0.f;

    float sbv[4];
#pragma unroll
    for (int g = 0; g < 4; ++g) sbv[g] = bss[g*128 + hb*16 + ty];

    float cst[4] = {0.f, 0.f, 0.f, 0.f};   // cell state, persistent in regs

    const float* zisb = g_zis + (size_t)b*OC*Hh*Ww;
    __syncthreads();

    for (int r = 0; r < Hh; ++r) {
        // load h_prev (all 128 channels of this b) — bypass L1 (stale-line risk)
        if (r > 0) {
            const float* hsrc = g_hbuf[r & 1] + b*HID*Ww;
#pragma unroll 4
            for (int it = 0; it < 32; ++it) {
                int idx = tid + it*256;
                hs[(idx >> 6)*68 + 1 + (idx & 63)] = __ldcg(&hsrc[idx]);
            }
        }
        // prefetch z_is for the gate phase (this thread: l=ty, w=wb..wb+3)
        float4 ziv[4];
#pragma unroll
        for (int g = 0; g < 4; ++g)
            ziv[g] = *reinterpret_cast<const float4*>(
                &zisb[(((size_t)(g*128 + hb*16 + ty))*Hh + r)*Ww + wb]);
        __syncthreads();

        // z_ss GEMM: acc over c, k. o paired (f32x2), 4 w per thread.
        unsigned long long acc[2][4];
#pragma unroll
        for (int jp = 0; jp < 2; ++jp)
#pragma unroll
            for (int i = 0; i < 4; ++i) acc[jp][i] = 0ull;

#pragma unroll 2
        for (int c = 0; c < 128; ++c) {
            const float* hrow = &hs[c*68 + wb];     // hrow[t] = h[wb-1+t]
            float4 h03 = *reinterpret_cast<const float4*>(hrow);
            float h4 = hrow[4], h5 = hrow[5];
            float hv[6] = {h03.x, h03.y, h03.z, h03.w, h4, h5};
            unsigned long long hp[6];
#pragma unroll
            for (int t = 0; t < 6; ++t) PACK2(hp[t], hv[t], hv[t]);
#pragma unroll
            for (int k = 0; k < 3; ++k) {
#pragma unroll
                for (int jp = 0; jp < 2; ++jp) {
                    unsigned long long wp = *reinterpret_cast<const unsigned long long*>(
                        &wk[k*8192 + c*64 + ty*4 + 2*jp]);
#pragma unroll
                    for (int i = 0; i < 4; ++i)
                        FMA2(acc[jp][i], wp, hp[i+k], acc[jp][i]);
                }
            }
        }

        // stage z_ss into zbuf[w][o_local] (pairs along o are contiguous)
#pragma unroll
        for (int jp = 0; jp < 2; ++jp)
#pragma unroll
            for (int i = 0; i < 4; ++i)
                *reinterpret_cast<unsigned long long*>(
                    &zbuf[(wb + i)*66 + ty*4 + 2*jp]) = acc[jp][i];
        __syncthreads();

        // gates for (ch = hb*16 + ty, w = wb..wb+3)
        float4 hres;
#pragma unroll
        for (int i = 0; i < 4; ++i) {
            int w = wb + i;
            float zi = zbuf[w*66 +  0 + ty] + sbv[0] + (&ziv[0].x)[i];
            float zf = zbuf[w*66 + 16 + ty] + sbv[1] + (&ziv[1].x)[i];
            float zo = zbuf[w*66 + 32 + ty] + sbv[2] + (&ziv[2].x)[i];
            float zg = zbuf[w*66 + 48 + ty] + sbv[3] + (&ziv[3].x)[i];
            float ig = 1.f / (1.f + __expf(-zi));
            float fg = 1.f / (1.f + __expf(-zf));
            float og = 1.f / (1.f + __expf(-zo));
            float gg = tanhf(zg);
            float cn = fg*cst[i] + ig*gg;
            cst[i] = cn;
            (&hres.x)[i] = og * tanhf(cn);
        }
        int chg = hb*16 + ty;
        __stcg(reinterpret_cast<float4*>(&g_hbuf[(r+1) & 1][(b*HID + chg)*Ww + wb]), hres);
        *reinterpret_cast<float4*>(&out[(((size_t)b*HID + chg)*Hh + r)*Ww + wb]) = hres;

        // grid barrier (all 128 CTAs co-resident: 1 CTA/SM by smem, grid<=148)
        __syncthreads();
        if (r < Hh - 1) {
            if (tid == 0) {
                __threadfence();
                atomicAdd((unsigned*)&g_bar, 1u);
                unsigned target = (unsigned)NCTA * (r + 1);
                while (g_bar < target) { }
                __threadfence();
            }
            __syncthreads();
        }
    }
}

// ---------------------------------------------------------------------------
extern "C" void kernel_launch(void* const* d_in, const int* in_sizes, int n_in,
                              void* d_out, int out_size) {
    const float* x   = (const float*)d_in[0];
    const float* Wis = (const float*)d_in[1];
    const float* bis = (const float*)d_in[2];
    const float* Wss = (const float*)d_in[3];
    const float* bss = (const float*)d_in[4];
    float* out = (float*)d_out;

    const int SMEM_A = 3*8192*sizeof(float);                       // 98304
    const int SMEM_P = (3*8192 + 128*68 + 64*66)*sizeof(float);    // 150016
    cudaFuncSetAttribute(kA_zis,  cudaFuncAttributeMaxDynamicSharedMemorySize, SMEM_A);
    cudaFuncSetAttribute(kP_rows, cudaFuncAttributeMaxDynamicSharedMemorySize, SMEM_P);

    init_kernel<<<1, 1>>>();

    dim3 gA(Bb*Hh, OC/64);
    kA_zis<<<gA, 256, SMEM_A>>>(x, Wis, bis);

    kP_rows<<<NCTA, 256, SMEM_P>>>(Wss, bss, out);
}